// round 1
// baseline (speedup 1.0000x reference)
#include <cuda_runtime.h>
#include <math.h>

#define EMB 256
#define VOCAB 50000
#define ROWS_OUT 101
#define NCTA_LSTM 8
#define BN_EPS 1e-5f

// ---------------- device scratch (no allocations allowed) ----------------
__device__ float g_wsum[1024 * EMB];      // W_ih + W_hh
__device__ float g_bsum[1024];            // b_ih + b_hh
__device__ float g_WlinT[361 * EMB];      // W_lin transposed [361][256]
__device__ float g_feat[EMB];
__device__ float g_H[ROWS_OUT * EMB];     // h vectors, row 0 = first cell
__device__ unsigned g_bar_gen;            // grid barrier generation
__device__ unsigned g_bar_cnt;            // grid barrier arrival count

// ---------------- K0: precompute Wsum, bsum, W_lin^T ----------------
__global__ void k0_precompute(const float* __restrict__ Wih,
                              const float* __restrict__ Whh,
                              const float* __restrict__ bih,
                              const float* __restrict__ bhh,
                              const float* __restrict__ Wlin) {
    int i = blockIdx.x * blockDim.x + threadIdx.x;
    int stride = gridDim.x * blockDim.x;
    for (int idx = i; idx < 1024 * EMB; idx += stride)
        g_wsum[idx] = Wih[idx] + Whh[idx];
    for (int idx = i; idx < 1024; idx += stride)
        g_bsum[idx] = bih[idx] + bhh[idx];
    for (int idx = i; idx < 361 * EMB; idx += stride) {
        int j = idx >> 8;        // 0..360
        int e = idx & 255;       // 0..255
        g_WlinT[idx] = Wlin[e * 361 + j];
    }
}

// ---------------- K1: conv/BN stack + feat (single CTA, 512 threads) ----------------
__global__ void k1_prep(const float* __restrict__ board,
                        const float* __restrict__ conv_w,
                        const float* __restrict__ conv_b,
                        const float* __restrict__ bn_gamma,
                        const float* __restrict__ bn_beta,
                        const float* __restrict__ p,
                        const float* __restrict__ b_lin) {
    __shared__ float A[441];   // 21x21 padded ping
    __shared__ float B[441];   // 21x21 padded pong
    __shared__ float d2s[361]; // residual carry / later d1 flat
    __shared__ float red[512]; // reduction buffer

    int tid = threadIdx.x;

    float w[9];
#pragma unroll
    for (int q = 0; q < 9; q++) w[q] = conv_w[q];
    float cbias = conv_b[0], gamma = bn_gamma[0], beta = bn_beta[0];

    if (tid < 441) { A[tid] = 0.f; B[tid] = 0.f; }
    __syncthreads();
    if (tid < 361) {
        int r = tid / 19, c = tid % 19;
        A[(r + 1) * 21 + (c + 1)] = board[tid];
    }
    __syncthreads();

    float* src = A;
    float* dst = B;

    // stage types: 0 = relu(ps*z), 1 = relu(ps*z + d2)->d2, 2 = relu(z)
    const int types[8] = {0, 0, 1, 0, 1, 0, 1, 2};
    const int pidx[8]  = {0, 1, 2, 3, 4, 5, 6, 0};

    for (int st = 0; st < 8; st++) {
        float y = 0.f;
        int base = 0;
        if (tid < 361) {
            int r = tid / 19, c = tid % 19;
            base = (r + 1) * 21 + (c + 1);
#pragma unroll
            for (int ki = 0; ki < 3; ki++)
#pragma unroll
                for (int kj = 0; kj < 3; kj++)
                    y += w[ki * 3 + kj] * src[base + (ki - 1) * 21 + (kj - 1)];
            y += cbias;
        }
        // mean over 361
        red[tid] = (tid < 361) ? y : 0.f;
        __syncthreads();
        for (int s = 256; s > 0; s >>= 1) {
            if (tid < s) red[tid] += red[tid + s];
            __syncthreads();
        }
        float mu = red[0] * (1.f / 361.f);
        __syncthreads();
        // variance (biased)
        float d = (tid < 361) ? (y - mu) : 0.f;
        red[tid] = d * d;
        __syncthreads();
        for (int s = 256; s > 0; s >>= 1) {
            if (tid < s) red[tid] += red[tid + s];
            __syncthreads();
        }
        float var = red[0] * (1.f / 361.f);
        float rstd = rsqrtf(var + BN_EPS);
        __syncthreads();

        if (tid < 361) {
            float z = gamma * (y - mu) * rstd + beta;
            float v;
            int t = types[st];
            if (t == 0)      v = fmaxf(p[pidx[st]] * z, 0.f);
            else if (t == 1) v = fmaxf(p[pidx[st]] * z + d2s[tid], 0.f);
            else             v = fmaxf(z, 0.f);
            dst[base] = v;
            if (st == 0 || t == 1) d2s[tid] = v;
        }
        __syncthreads();
        float* tmp = src; src = dst; dst = tmp;
    }

    // flatten final d1 (now in src) into d2s
    if (tid < 361) {
        int r = tid / 19, c = tid % 19;
        d2s[tid] = src[(r + 1) * 21 + (c + 1)];
    }
    __syncthreads();

    // feat = W_lin @ d1 + b_lin  (coalesced via transposed weights)
    if (tid < 256) {
        float acc = b_lin[tid];
        for (int j = 0; j < 361; j++)
            acc += g_WlinT[j * 256 + tid] * d2s[j];
        g_feat[tid] = acc;
    }
}

// ---------------- grid barrier for K2 ----------------
__device__ __forceinline__ void grid_barrier() {
    __syncthreads();
    if (threadIdx.x == 0) {
        unsigned snap = atomicAdd(&g_bar_gen, 0u);
        unsigned prev = atomicAdd(&g_bar_cnt, 1u);
        if (prev == NCTA_LSTM - 1) {
            atomicExch(&g_bar_cnt, 0u);
            __threadfence();
            atomicAdd(&g_bar_gen, 1u);
        } else {
            while ((int)(atomicAdd(&g_bar_gen, 0u) - snap) <= 0) {
                __nanosleep(32);
            }
        }
        __threadfence();
    }
    __syncthreads();
}

__device__ __forceinline__ float sigmoidf_(float x) {
    return 1.f / (1.f + expf(-x));
}

// ---------------- K2: persistent LSTM recurrence (8 CTAs x 256 thr) ----------------
// CTA b owns h indices [b*32, b*32+32). Owns 128 gate rows (i,f,g,o sections).
// SMEM holds its 128x256 slice of Wsum (XOR-swizzled float4 layout).
__global__ void k2_lstm(const float* __restrict__ Wih) {
    extern __shared__ float sm[];
    float* ws  = sm;                 // 32768 floats (128 rows * 256)
    float* h_s = sm + 32768;         // 256
    float* bs  = h_s + 256;          // 128
    float* pp  = bs + 128;           // 256 partials
    float* g4v = pp + 256;           // 128 gate pre-activations
    float* c_s = g4v + 128;          // 32 cell states

    int tid = threadIdx.x;
    int b = blockIdx.x;
    int jbase = b * 32;

    if (tid < 128) {
        int sec = tid >> 5, j = tid & 31;
        bs[tid] = g_bsum[sec * 256 + jbase + j];
    }
    // load Wsum slice into swizzled smem (8192 float4s)
    {
        const float4* W4 = (const float4*)g_wsum;
        float4* ws4 = (float4*)ws;
        for (int q = tid; q < 8192; q += 256) {
            int l = q >> 6;              // local row 0..127
            int k4 = q & 63;             // float4 column
            int sec = l >> 5, j = l & 31;
            int grow = sec * 256 + jbase + j;
            float4 v = W4[grow * 64 + k4];
            ws4[l * 64 + (k4 ^ (l & 7))] = v;
        }
    }
    if (tid < 32) c_s[tid] = 0.f;
    h_s[tid] = g_feat[tid];
    __syncthreads();

    int half = tid >> 7;       // 0 or 1
    int l = tid & 127;         // local gate row
    int sec = l >> 5, j = l & 31;
    int grow = sec * 256 + jbase + j;
    int swz = l & 7;

    // ---- step 0: gates = W_ih @ feat + bsum (h = c = 0) ----
    {
        float acc = 0.f;
        const float4* Wr = (const float4*)(Wih + grow * 256 + half * 128);
        const float4* hv = (const float4*)(h_s + half * 128);
#pragma unroll 8
        for (int k = 0; k < 32; k++) {
            float4 wv = Wr[k];
            float4 xv = hv[k];
            acc += wv.x * xv.x + wv.y * xv.y + wv.z * xv.z + wv.w * xv.w;
        }
        pp[tid] = acc;
    }
    __syncthreads();
    if (tid < 128) g4v[tid] = pp[tid] + pp[tid + 128] + bs[tid];
    __syncthreads();
    if (tid < 32) {
        float ig = sigmoidf_(g4v[tid]);
        float fg = sigmoidf_(g4v[32 + tid]);
        float gg = tanhf(g4v[64 + tid]);
        float og = sigmoidf_(g4v[96 + tid]);
        float c = fg * c_s[tid] + ig * gg;
        c_s[tid] = c;
        g_H[jbase + tid] = og * tanhf(c);
    }
    __threadfence();
    grid_barrier();

    // ---- steps 1..100: gates = Wsum @ h_prev + bsum ----
    const float4* ws4 = (const float4*)ws;
    for (int s = 1; s <= 100; s++) {
        h_s[tid] = g_H[(s - 1) * 256 + tid];
        __syncthreads();
        float acc = 0.f;
        const float4* hv = (const float4*)(h_s + half * 128);
        int rowbase = l * 64;
        int kbase = half * 32;
#pragma unroll 8
        for (int kk = 0; kk < 32; kk++) {
            float4 wv = ws4[rowbase + ((kbase + kk) ^ swz)];
            float4 xv = hv[kk];
            acc += wv.x * xv.x + wv.y * xv.y + wv.z * xv.z + wv.w * xv.w;
        }
        pp[tid] = acc;
        __syncthreads();
        if (tid < 128) g4v[tid] = pp[tid] + pp[tid + 128] + bs[tid];
        __syncthreads();
        if (tid < 32) {
            float ig = sigmoidf_(g4v[tid]);
            float fg = sigmoidf_(g4v[32 + tid]);
            float gg = tanhf(g4v[64 + tid]);
            float og = sigmoidf_(g4v[96 + tid]);
            float c = fg * c_s[tid] + ig * gg;
            c_s[tid] = c;
            g_H[s * 256 + jbase + tid] = og * tanhf(c);
        }
        __threadfence();
        grid_barrier();
    }
}

// ---------------- K3: OUT[101,50000] = relu(H @ W_dec^T + b_dec) ----------------
// CTA: 128 vocab cols. Thread: 13 rows x 4 vocab. Warp = one row-group ->
// all H reads are SMEM broadcasts.
__global__ void k3_decode(const float* __restrict__ W_dec,
                          const float* __restrict__ b_dec,
                          float* __restrict__ out) {
    extern __shared__ float sm[];
    float* Hs = sm;            // 104*256 floats
    float* Ws = sm + 104 * 256; // 32*128 floats

    int tid = threadIdx.x;
    int vbase = blockIdx.x * 128;

    for (int i = tid; i < 101 * 256; i += 256) Hs[i] = g_H[i];
    for (int i = 101 * 256 + tid; i < 104 * 256; i += 256) Hs[i] = 0.f;

    int vg = tid & 31;         // vocab quad 0..31
    int rg = tid >> 5;         // row group 0..7 (rows rg*13..rg*13+12)
    int v0 = vbase + vg * 4;

    float acc[13][4];
#pragma unroll
    for (int r = 0; r < 13; r++) {
        acc[r][0] = 0.f; acc[r][1] = 0.f; acc[r][2] = 0.f; acc[r][3] = 0.f;
    }

    const float4* Wd4 = (const float4*)W_dec;
    const float4* Ws4 = (const float4*)Ws;

    for (int kc = 0; kc < 8; kc++) {
        __syncthreads();
        // stage W tile [32 k][128 vocab]
#pragma unroll
        for (int q = 0; q < 4; q++) {
            int F = tid + 256 * q;         // 0..1023
            int vcol = F >> 3;             // 0..127
            int kq = F & 7;                // float4 idx within k-chunk
            int v = vbase + vcol;
            float4 val = make_float4(0.f, 0.f, 0.f, 0.f);
            if (v < VOCAB) val = Wd4[v * 64 + kc * 8 + kq];
            Ws[(kq * 4 + 0) * 128 + vcol] = val.x;
            Ws[(kq * 4 + 1) * 128 + vcol] = val.y;
            Ws[(kq * 4 + 2) * 128 + vcol] = val.z;
            Ws[(kq * 4 + 3) * 128 + vcol] = val.w;
        }
        __syncthreads();
#pragma unroll
        for (int kk = 0; kk < 32; kk++) {
            float4 wv = Ws4[kk * 32 + vg];
            int k = kc * 32 + kk;
#pragma unroll
            for (int r = 0; r < 13; r++) {
                float hv = Hs[(rg * 13 + r) * 256 + k];
                acc[r][0] += hv * wv.x;
                acc[r][1] += hv * wv.y;
                acc[r][2] += hv * wv.z;
                acc[r][3] += hv * wv.w;
            }
        }
    }

    float4 bv = make_float4(0.f, 0.f, 0.f, 0.f);
    if (v0 < VOCAB) bv = ((const float4*)b_dec)[v0 >> 2];
#pragma unroll
    for (int r = 0; r < 13; r++) {
        int row = rg * 13 + r;
        if (row < ROWS_OUT && v0 < VOCAB) {
            float4 o;
            o.x = fmaxf(acc[r][0] + bv.x, 0.f);
            o.y = fmaxf(acc[r][1] + bv.y, 0.f);
            o.z = fmaxf(acc[r][2] + bv.z, 0.f);
            o.w = fmaxf(acc[r][3] + bv.w, 0.f);
            ((float4*)out)[(row * VOCAB + v0) >> 2] = o;
        }
    }
}

// ---------------- launch ----------------
extern "C" void kernel_launch(void* const* d_in, const int* in_sizes, int n_in,
                              void* d_out, int out_size) {
    const float* board    = (const float*)d_in[0];
    const float* conv_w   = (const float*)d_in[1];
    const float* conv_b   = (const float*)d_in[2];
    const float* bn_gamma = (const float*)d_in[3];
    const float* bn_beta  = (const float*)d_in[4];
    const float* p        = (const float*)d_in[5];
    const float* W_lin    = (const float*)d_in[6];
    const float* b_lin    = (const float*)d_in[7];
    const float* W_ih     = (const float*)d_in[8];
    const float* b_ih     = (const float*)d_in[9];
    const float* W_hh     = (const float*)d_in[10];
    const float* b_hh     = (const float*)d_in[11];
    const float* W_dec    = (const float*)d_in[12];
    const float* b_dec    = (const float*)d_in[13];
    float* out = (float*)d_out;

    size_t sm2 = (size_t)(32768 + 256 + 128 + 256 + 128 + 32) * sizeof(float);
    size_t sm3 = (size_t)(104 * 256 + 32 * 128) * sizeof(float);
    cudaFuncSetAttribute(k2_lstm,  cudaFuncAttributeMaxDynamicSharedMemorySize, (int)sm2);
    cudaFuncSetAttribute(k3_decode, cudaFuncAttributeMaxDynamicSharedMemorySize, (int)sm3);

    k0_precompute<<<256, 256>>>(W_ih, W_hh, b_ih, b_hh, W_lin);
    k1_prep<<<1, 512>>>(board, conv_w, conv_b, bn_gamma, bn_beta, p, b_lin);
    k2_lstm<<<NCTA_LSTM, 256, sm2>>>(W_ih);
    k3_decode<<<(VOCAB + 127) / 128, 256, sm3>>>(W_dec, b_dec, out);
}

// round 2
// speedup vs baseline: 2.4059x; 2.4059x over previous
#include <cuda_runtime.h>
#include <math.h>

#define EMB 256
#define VOCAB 50000
#define ROWS_OUT 101
#define BN_EPS 1e-5f

// ---------------- packed f32x2 helpers ----------------
#define FMA2(acc, a, b) \
    asm("fma.rn.f32x2 %0, %1, %2, %0;" : "+l"(acc) : "l"(a), "l"(b))
#define UNPACK64(lo, hi, v) do { unsigned _ulo, _uhi; \
    asm("mov.b64 {%0, %1}, %2;" : "=r"(_ulo), "=r"(_uhi) : "l"(v)); \
    lo = __uint_as_float(_ulo); hi = __uint_as_float(_uhi); } while (0)
#define DUP2(d, f) do { unsigned _u = __float_as_uint(f); \
    asm("mov.b64 %0, {%1, %1};" : "=l"(d) : "r"(_u)); } while (0)

// ---------------- device scratch ----------------
__device__ float g_wsum[1024 * EMB];      // W_ih + W_hh
__device__ float g_bsum[1024];            // b_ih + b_hh
__device__ float g_WlinT[361 * EMB];      // W_lin transposed [361][256]
__device__ float g_feat[EMB];
__device__ float g_H[ROWS_OUT * EMB];     // h vectors

// ---------------- K0: precompute Wsum, bsum, W_lin^T ----------------
__global__ void k0_precompute(const float* __restrict__ Wih,
                              const float* __restrict__ Whh,
                              const float* __restrict__ bih,
                              const float* __restrict__ bhh,
                              const float* __restrict__ Wlin) {
    int i = blockIdx.x * blockDim.x + threadIdx.x;
    int stride = gridDim.x * blockDim.x;
    for (int idx = i; idx < 1024 * EMB; idx += stride)
        g_wsum[idx] = Wih[idx] + Whh[idx];
    for (int idx = i; idx < 1024; idx += stride)
        g_bsum[idx] = bih[idx] + bhh[idx];
    for (int idx = i; idx < 361 * EMB; idx += stride) {
        int j = idx >> 8;
        int e = idx & 255;
        g_WlinT[idx] = Wlin[e * 361 + j];
    }
}

// ---------------- K1: conv/BN stack + feat (single CTA, 512 threads) ----------------
__device__ __forceinline__ float block_sum512(float v, float* red16) {
#pragma unroll
    for (int o = 16; o; o >>= 1) v += __shfl_xor_sync(0xffffffffu, v, o);
    __syncthreads();                         // prior reads of red16 done
    if ((threadIdx.x & 31) == 0) red16[threadIdx.x >> 5] = v;
    __syncthreads();
    float s = 0.f;
#pragma unroll
    for (int i = 0; i < 16; i++) s += red16[i];
    return s;
}

__global__ void k1_prep(const float* __restrict__ board,
                        const float* __restrict__ conv_w,
                        const float* __restrict__ conv_b,
                        const float* __restrict__ bn_gamma,
                        const float* __restrict__ bn_beta,
                        const float* __restrict__ p,
                        const float* __restrict__ b_lin) {
    __shared__ float A[441];
    __shared__ float B[441];
    __shared__ float d2s[361];
    __shared__ float red16[16];

    int tid = threadIdx.x;

    float w[9];
#pragma unroll
    for (int q = 0; q < 9; q++) w[q] = conv_w[q];
    float cbias = conv_b[0], gamma = bn_gamma[0], beta = bn_beta[0];

    if (tid < 441) { A[tid] = 0.f; B[tid] = 0.f; }
    __syncthreads();
    if (tid < 361) {
        int r = tid / 19, c = tid % 19;
        A[(r + 1) * 21 + (c + 1)] = board[tid];
    }
    __syncthreads();

    float* src = A;
    float* dst = B;

    const int types[8] = {0, 0, 1, 0, 1, 0, 1, 2};
    const int pidx[8]  = {0, 1, 2, 3, 4, 5, 6, 0};

    for (int st = 0; st < 8; st++) {
        float y = 0.f;
        int base = 0;
        if (tid < 361) {
            int r = tid / 19, c = tid % 19;
            base = (r + 1) * 21 + (c + 1);
#pragma unroll
            for (int ki = 0; ki < 3; ki++)
#pragma unroll
                for (int kj = 0; kj < 3; kj++)
                    y += w[ki * 3 + kj] * src[base + (ki - 1) * 21 + (kj - 1)];
            y += cbias;
        }
        float mu = block_sum512((tid < 361) ? y : 0.f, red16) * (1.f / 361.f);
        float d = (tid < 361) ? (y - mu) : 0.f;
        float var = block_sum512(d * d, red16) * (1.f / 361.f);
        float rstd = rsqrtf(var + BN_EPS);

        if (tid < 361) {
            float z = gamma * (y - mu) * rstd + beta;
            float v;
            int t = types[st];
            if (t == 0)      v = fmaxf(p[pidx[st]] * z, 0.f);
            else if (t == 1) v = fmaxf(p[pidx[st]] * z + d2s[tid], 0.f);
            else             v = fmaxf(z, 0.f);
            dst[base] = v;
            if (st == 0 || t == 1) d2s[tid] = v;
        }
        __syncthreads();
        float* tmp = src; src = dst; dst = tmp;
    }

    if (tid < 361) {
        int r = tid / 19, c = tid % 19;
        d2s[tid] = src[(r + 1) * 21 + (c + 1)];
    }
    __syncthreads();

    if (tid < 256) {
        float acc = b_lin[tid];
        for (int j = 0; j < 361; j++)
            acc += g_WlinT[j * 256 + tid] * d2s[j];
        g_feat[tid] = acc;
    }
}

// ---------------- K2: cluster-of-8 persistent LSTM ----------------
__device__ __forceinline__ void cluster_sync_() {
    asm volatile("barrier.cluster.arrive.aligned;" ::: "memory");
    asm volatile("barrier.cluster.wait.aligned;" ::: "memory");
}
__device__ __forceinline__ unsigned smem_u32(const void* p) {
    unsigned a;
    asm("{ .reg .u64 t; cvta.to.shared.u64 t, %1; cvt.u32.u64 %0, t; }"
        : "=r"(a) : "l"(p));
    return a;
}
__device__ __forceinline__ void st_cluster_f32(unsigned addr, int rank, float v) {
    unsigned r;
    asm volatile("mapa.shared::cluster.u32 %0, %1, %2;" : "=r"(r) : "r"(addr), "r"(rank));
    asm volatile("st.shared::cluster.f32 [%0], %1;" :: "r"(r), "f"(v) : "memory");
}
__device__ __forceinline__ float sigmoidf_(float x) {
    return 1.f / (1.f + expf(-x));
}

// CTA b owns h[b*32 .. b*32+31] and 128 gate rows. Weights (f32x2-packed)
// live in registers; h broadcast every step via DSMEM; cluster barrier syncs.
__global__ void __cluster_dims__(8, 1, 1) __launch_bounds__(256, 1)
k2_lstm(const float* __restrict__ Wih) {
    __shared__ __align__(16) float h_buf[2][256];
    __shared__ float g4v[128];
    __shared__ float bs[128];
    __shared__ float c_s[32];

    int tid = threadIdx.x;
    int b = blockIdx.x;                 // cluster rank
    int jbase = b * 32;
    int lane = tid & 31, wid = tid >> 5;
    int half = lane >> 4;               // k-half
    int rloc = wid * 16 + (lane & 15);  // local gate row 0..127
    int sec = rloc >> 5, j = rloc & 31;
    int grow = sec * 256 + jbase + j;   // global gate row

    if (tid < 128) bs[tid] = g_bsum[(tid >> 5) * 256 + jbase + (tid & 31)];
    if (tid < 32) c_s[tid] = 0.f;
    h_buf[0][tid] = g_feat[tid];

    // weights into registers (64 packed f32x2 per thread = 128 floats)
    unsigned long long wregu[64];
    {
        const ulonglong2* wp = (const ulonglong2*)(g_wsum + grow * 256 + half * 128);
#pragma unroll
        for (int q = 0; q < 32; q++) {
            ulonglong2 t = wp[q];
            wregu[2 * q] = t.x; wregu[2 * q + 1] = t.y;
        }
    }
    __syncthreads();
    cluster_sync_();

    // ---- step 0: gates = W_ih @ feat (h=c=0) ----
    {
        unsigned long long a0 = 0ull, a1 = 0ull;
        const ulonglong2* wp = (const ulonglong2*)(Wih + grow * 256 + half * 128);
        const ulonglong2* hu = (const ulonglong2*)(&h_buf[0][half * 128]);
#pragma unroll
        for (int q = 0; q < 32; q++) {
            ulonglong2 wv = wp[q];
            ulonglong2 hx = hu[q];
            FMA2(a0, wv.x, hx.x);
            FMA2(a1, wv.y, hx.y);
        }
        float l0, h0, l1, h1;
        UNPACK64(l0, h0, a0);
        UNPACK64(l1, h1, a1);
        float acc = (l0 + h0) + (l1 + h1);
        acc += __shfl_xor_sync(0xffffffffu, acc, 16);
        if (half == 0) g4v[rloc] = acc;
    }
    __syncthreads();
    if (tid < 32) {
        float gi = sigmoidf_(g4v[tid] + bs[tid]);
        float gf = sigmoidf_(g4v[32 + tid] + bs[32 + tid]);
        float gg = tanhf(g4v[64 + tid] + bs[64 + tid]);
        float go = sigmoidf_(g4v[96 + tid] + bs[96 + tid]);
        float c = gf * c_s[tid] + gi * gg;
        c_s[tid] = c;
        float h = go * tanhf(c);
        g_H[jbase + tid] = h;
        unsigned addr = smem_u32(&h_buf[1][jbase + tid]);
#pragma unroll
        for (int rk = 0; rk < 8; rk++) st_cluster_f32(addr, rk, h);
    }
    cluster_sync_();

    // ---- steps 1..100: gates = Wsum @ h_prev ----
    int cur = 1;
    for (int s = 1; s <= 100; s++) {
        unsigned long long a0 = 0ull, a1 = 0ull;
        const ulonglong2* hu = (const ulonglong2*)(&h_buf[cur][half * 128]);
#pragma unroll
        for (int q = 0; q < 32; q++) {
            ulonglong2 hx = hu[q];
            FMA2(a0, wregu[2 * q], hx.x);
            FMA2(a1, wregu[2 * q + 1], hx.y);
        }
        float l0, h0, l1, h1;
        UNPACK64(l0, h0, a0);
        UNPACK64(l1, h1, a1);
        float acc = (l0 + h0) + (l1 + h1);
        acc += __shfl_xor_sync(0xffffffffu, acc, 16);
        if (half == 0) g4v[rloc] = acc;
        __syncthreads();
        if (tid < 32) {
            float gi = sigmoidf_(g4v[tid] + bs[tid]);
            float gf = sigmoidf_(g4v[32 + tid] + bs[32 + tid]);
            float gg = tanhf(g4v[64 + tid] + bs[64 + tid]);
            float go = sigmoidf_(g4v[96 + tid] + bs[96 + tid]);
            float c = gf * c_s[tid] + gi * gg;
            c_s[tid] = c;
            float h = go * tanhf(c);
            g_H[s * 256 + jbase + tid] = h;
            unsigned addr = smem_u32(&h_buf[cur ^ 1][jbase + tid]);
#pragma unroll
            for (int rk = 0; rk < 8; rk++) st_cluster_f32(addr, rk, h);
        }
        cluster_sync_();
        cur ^= 1;
    }
}

// ---------------- K3: OUT[101,50000] = relu(H @ W_dec^T + b_dec) ----------------
// CTA: 128 vocab. Thread: 13 rows (6 f32x2 pairs + 1 scalar) x 4 vocab.
// H staged per-32k-chunk transposed [k][row] so row pairs are natural LDS.64.
#define HS_STRIDE 114   // 112 row slots + 2 pad (even, ~conflict-free staging)

__global__ void __launch_bounds__(256, 2)
k3_decode(const float* __restrict__ W_dec,
          const float* __restrict__ b_dec,
          float* __restrict__ out) {
    __shared__ __align__(16) float Hs[32 * HS_STRIDE];  // [k][row-slot]
    __shared__ __align__(16) float Ws[32 * 128];        // [k][vocab]

    int tid = threadIdx.x;
    int vbase = blockIdx.x * 128;
    int vg = tid & 31;          // vocab quad
    int rg = tid >> 5;          // row group (rows rg*13 .. rg*13+12)
    int v0 = vbase + vg * 4;

    unsigned long long acc[6][4];
#pragma unroll
    for (int q = 0; q < 6; q++)
#pragma unroll
        for (int c = 0; c < 4; c++) acc[q][c] = 0ull;
    float acc12[4] = {0.f, 0.f, 0.f, 0.f};

    const float4* Wd4 = (const float4*)W_dec;

    for (int kc = 0; kc < 8; kc++) {
        __syncthreads();
        // stage H chunk transposed: slot s in group g holds row g*13+r (r<13), slot 13 = 0
        for (int i = tid; i < 32 * 112; i += 256) {
            int kk = i & 31;
            int srow = i >> 5;           // 0..111
            int g = srow / 14;
            int r = srow - g * 14;
            int actual = g * 13 + r;
            float v = 0.f;
            if (r < 13 && actual < ROWS_OUT)
                v = g_H[actual * 256 + kc * 32 + kk];
            Hs[kk * HS_STRIDE + srow] = v;
        }
        // stage W tile [32k][128v]
#pragma unroll
        for (int q = 0; q < 4; q++) {
            int F = tid + 256 * q;
            int vcol = F >> 3;
            int kq = F & 7;
            int v = vbase + vcol;
            float4 val = make_float4(0.f, 0.f, 0.f, 0.f);
            if (v < VOCAB) val = Wd4[v * 64 + kc * 8 + kq];
            Ws[(kq * 4 + 0) * 128 + vcol] = val.x;
            Ws[(kq * 4 + 1) * 128 + vcol] = val.y;
            Ws[(kq * 4 + 2) * 128 + vcol] = val.z;
            Ws[(kq * 4 + 3) * 128 + vcol] = val.w;
        }
        __syncthreads();

#pragma unroll
        for (int kk = 0; kk < 32; kk++) {
            float4 wv = *(const float4*)(Ws + kk * 128 + vg * 4);
            unsigned long long wx, wy, wz, ww;
            DUP2(wx, wv.x); DUP2(wy, wv.y); DUP2(wz, wv.z); DUP2(ww, wv.w);
            const unsigned long long* hp =
                (const unsigned long long*)(Hs + kk * HS_STRIDE + rg * 14);
#pragma unroll
            for (int q = 0; q < 6; q++) {
                unsigned long long hq = hp[q];
                FMA2(acc[q][0], hq, wx);
                FMA2(acc[q][1], hq, wy);
                FMA2(acc[q][2], hq, wz);
                FMA2(acc[q][3], hq, ww);
            }
            float h12 = Hs[kk * HS_STRIDE + rg * 14 + 12];
            acc12[0] = fmaf(h12, wv.x, acc12[0]);
            acc12[1] = fmaf(h12, wv.y, acc12[1]);
            acc12[2] = fmaf(h12, wv.z, acc12[2]);
            acc12[3] = fmaf(h12, wv.w, acc12[3]);
        }
    }

    bool vok = (v0 < VOCAB);
    float4 bv = make_float4(0.f, 0.f, 0.f, 0.f);
    if (vok) bv = ((const float4*)b_dec)[v0 >> 2];
    float bb[4] = {bv.x, bv.y, bv.z, bv.w};

#pragma unroll
    for (int q = 0; q < 6; q++) {
        int r0 = rg * 13 + 2 * q;
        float lo[4], hi[4];
#pragma unroll
        for (int c = 0; c < 4; c++) {
            UNPACK64(lo[c], hi[c], acc[q][c]);
            lo[c] = fmaxf(lo[c] + bb[c], 0.f);
            hi[c] = fmaxf(hi[c] + bb[c], 0.f);
        }
        if (vok && r0 < ROWS_OUT) {
            float4 o = make_float4(lo[0], lo[1], lo[2], lo[3]);
            *(float4*)(out + r0 * VOCAB + v0) = o;
        }
        if (vok && r0 + 1 < ROWS_OUT) {
            float4 o = make_float4(hi[0], hi[1], hi[2], hi[3]);
            *(float4*)(out + (r0 + 1) * VOCAB + v0) = o;
        }
    }
    int r12 = rg * 13 + 12;
    if (vok && r12 < ROWS_OUT) {
        float4 o;
        o.x = fmaxf(acc12[0] + bb[0], 0.f);
        o.y = fmaxf(acc12[1] + bb[1], 0.f);
        o.z = fmaxf(acc12[2] + bb[2], 0.f);
        o.w = fmaxf(acc12[3] + bb[3], 0.f);
        *(float4*)(out + r12 * VOCAB + v0) = o;
    }
}

// ---------------- launch ----------------
extern "C" void kernel_launch(void* const* d_in, const int* in_sizes, int n_in,
                              void* d_out, int out_size) {
    const float* board    = (const float*)d_in[0];
    const float* conv_w   = (const float*)d_in[1];
    const float* conv_b   = (const float*)d_in[2];
    const float* bn_gamma = (const float*)d_in[3];
    const float* bn_beta  = (const float*)d_in[4];
    const float* p        = (const float*)d_in[5];
    const float* W_lin    = (const float*)d_in[6];
    const float* b_lin    = (const float*)d_in[7];
    const float* W_ih     = (const float*)d_in[8];
    const float* b_ih     = (const float*)d_in[9];
    const float* W_hh     = (const float*)d_in[10];
    const float* b_hh     = (const float*)d_in[11];
    const float* W_dec    = (const float*)d_in[12];
    const float* b_dec    = (const float*)d_in[13];
    float* out = (float*)d_out;

    k0_precompute<<<256, 256>>>(W_ih, W_hh, b_ih, b_hh, W_lin);
    k1_prep<<<1, 512>>>(board, conv_w, conv_b, bn_gamma, bn_beta, p, b_lin);
    k2_lstm<<<8, 256>>>(W_ih);
    k3_decode<<<(VOCAB + 127) / 128, 256>>>(W_dec, b_dec, out);
}

// round 3
// speedup vs baseline: 2.6037x; 1.0822x over previous
#include <cuda_runtime.h>
#include <math.h>

#define EMB 256
#define VOCAB 50000
#define ROWS_OUT 101
#define BN_EPS 1e-5f

// ---------------- packed f32x2 helpers ----------------
#define FMA2(acc, a, b) \
    asm("fma.rn.f32x2 %0, %1, %2, %0;" : "+l"(acc) : "l"(a), "l"(b))
#define UNPACK64(lo, hi, v) do { unsigned _ulo, _uhi; \
    asm("mov.b64 {%0, %1}, %2;" : "=r"(_ulo), "=r"(_uhi) : "l"(v)); \
    lo = __uint_as_float(_ulo); hi = __uint_as_float(_uhi); } while (0)
#define DUP2(d, f) do { unsigned _u = __float_as_uint(f); \
    asm("mov.b64 %0, {%1, %1};" : "=l"(d) : "r"(_u)); } while (0)

// ---------------- device scratch ----------------
__device__ float g_wsum[1024 * EMB];      // W_ih + W_hh
__device__ float g_bsum[1024];            // b_ih + b_hh
__device__ float g_WlinT[361 * EMB];      // W_lin transposed
__device__ float g_feat[EMB];
__device__ float g_H[ROWS_OUT * EMB];     // h vectors

// ---------------- K0 ----------------
__global__ void k0_precompute(const float* __restrict__ Wih,
                              const float* __restrict__ Whh,
                              const float* __restrict__ bih,
                              const float* __restrict__ bhh,
                              const float* __restrict__ Wlin) {
    int i = blockIdx.x * blockDim.x + threadIdx.x;
    int stride = gridDim.x * blockDim.x;
    for (int idx = i; idx < 1024 * EMB; idx += stride)
        g_wsum[idx] = Wih[idx] + Whh[idx];
    for (int idx = i; idx < 1024; idx += stride)
        g_bsum[idx] = bih[idx] + bhh[idx];
    for (int idx = i; idx < 361 * EMB; idx += stride) {
        int j = idx >> 8;
        int e = idx & 255;
        g_WlinT[idx] = Wlin[e * 361 + j];
    }
}

// ---------------- K1 ----------------
__device__ __forceinline__ float block_sum512(float v, float* red16) {
#pragma unroll
    for (int o = 16; o; o >>= 1) v += __shfl_xor_sync(0xffffffffu, v, o);
    __syncthreads();
    if ((threadIdx.x & 31) == 0) red16[threadIdx.x >> 5] = v;
    __syncthreads();
    float s = 0.f;
#pragma unroll
    for (int i = 0; i < 16; i++) s += red16[i];
    return s;
}

__global__ void k1_prep(const float* __restrict__ board,
                        const float* __restrict__ conv_w,
                        const float* __restrict__ conv_b,
                        const float* __restrict__ bn_gamma,
                        const float* __restrict__ bn_beta,
                        const float* __restrict__ p,
                        const float* __restrict__ b_lin) {
    __shared__ float A[441];
    __shared__ float B[441];
    __shared__ float d2s[361];
    __shared__ float red16[16];

    int tid = threadIdx.x;

    float w[9];
#pragma unroll
    for (int q = 0; q < 9; q++) w[q] = conv_w[q];
    float cbias = conv_b[0], gamma = bn_gamma[0], beta = bn_beta[0];

    if (tid < 441) { A[tid] = 0.f; B[tid] = 0.f; }
    __syncthreads();
    if (tid < 361) {
        int r = tid / 19, c = tid % 19;
        A[(r + 1) * 21 + (c + 1)] = board[tid];
    }
    __syncthreads();

    float* src = A;
    float* dst = B;

    const int types[8] = {0, 0, 1, 0, 1, 0, 1, 2};
    const int pidx[8]  = {0, 1, 2, 3, 4, 5, 6, 0};

    for (int st = 0; st < 8; st++) {
        float y = 0.f;
        int base = 0;
        if (tid < 361) {
            int r = tid / 19, c = tid % 19;
            base = (r + 1) * 21 + (c + 1);
#pragma unroll
            for (int ki = 0; ki < 3; ki++)
#pragma unroll
                for (int kj = 0; kj < 3; kj++)
                    y += w[ki * 3 + kj] * src[base + (ki - 1) * 21 + (kj - 1)];
            y += cbias;
        }
        float mu = block_sum512((tid < 361) ? y : 0.f, red16) * (1.f / 361.f);
        float d = (tid < 361) ? (y - mu) : 0.f;
        float var = block_sum512(d * d, red16) * (1.f / 361.f);
        float rstd = rsqrtf(var + BN_EPS);

        if (tid < 361) {
            float z = gamma * (y - mu) * rstd + beta;
            float v;
            int t = types[st];
            if (t == 0)      v = fmaxf(p[pidx[st]] * z, 0.f);
            else if (t == 1) v = fmaxf(p[pidx[st]] * z + d2s[tid], 0.f);
            else             v = fmaxf(z, 0.f);
            dst[base] = v;
            if (st == 0 || t == 1) d2s[tid] = v;
        }
        __syncthreads();
        float* tmp = src; src = dst; dst = tmp;
    }

    if (tid < 361) {
        int r = tid / 19, c = tid % 19;
        d2s[tid] = src[(r + 1) * 21 + (c + 1)];
    }
    __syncthreads();

    if (tid < 256) {
        float acc = b_lin[tid];
        for (int j = 0; j < 361; j++)
            acc += g_WlinT[j * 256 + tid] * d2s[j];
        g_feat[tid] = acc;
    }
}

// ---------------- K2: cluster-of-8 LSTM, mbarrier + st.async ----------------
__device__ __forceinline__ void cluster_sync_() {
    asm volatile("barrier.cluster.arrive.aligned;" ::: "memory");
    asm volatile("barrier.cluster.wait.aligned;" ::: "memory");
}
__device__ __forceinline__ unsigned smem_u32(const void* p) {
    unsigned a;
    asm("{ .reg .u64 t; cvta.to.shared.u64 t, %1; cvt.u32.u64 %0, t; }"
        : "=r"(a) : "l"(p));
    return a;
}
__device__ __forceinline__ void mbar_init_(unsigned addr, unsigned cnt) {
    asm volatile("mbarrier.init.shared.b64 [%0], %1;" :: "r"(addr), "r"(cnt) : "memory");
}
__device__ __forceinline__ void mbar_arrive_expect(unsigned addr, unsigned tx) {
    asm volatile("mbarrier.arrive.expect_tx.shared.b64 _, [%0], %1;"
                 :: "r"(addr), "r"(tx) : "memory");
}
__device__ __forceinline__ void mbar_wait_cluster(unsigned addr, unsigned parity) {
    unsigned done;
    asm volatile(
        "{\n\t.reg .pred p;\n\t"
        "mbarrier.try_wait.parity.acquire.cluster.shared::cta.b64 p, [%1], %2, 0x989680;\n\t"
        "selp.b32 %0, 1, 0, p;\n\t}"
        : "=r"(done) : "r"(addr), "r"(parity) : "memory");
    while (!done) {
        asm volatile(
            "{\n\t.reg .pred p;\n\t"
            "mbarrier.try_wait.parity.acquire.cluster.shared::cta.b64 p, [%1], %2, 0x989680;\n\t"
            "selp.b32 %0, 1, 0, p;\n\t}"
            : "=r"(done) : "r"(addr), "r"(parity) : "memory");
    }
}
__device__ __forceinline__ void st_async_remote(unsigned daddr, unsigned dmbar,
                                                int rk, float v) {
    unsigned ra, rm;
    asm volatile("mapa.shared::cluster.u32 %0, %1, %2;" : "=r"(ra) : "r"(daddr), "r"(rk));
    asm volatile("mapa.shared::cluster.u32 %0, %1, %2;" : "=r"(rm) : "r"(dmbar), "r"(rk));
    asm volatile("st.async.shared::cluster.mbarrier::complete_tx::bytes.f32 [%0], %1, [%2];"
                 :: "r"(ra), "f"(v), "r"(rm) : "memory");
}
__device__ __forceinline__ float sigmoidf_(float x) {
    return 1.f / (1.f + expf(-x));
}

// thread = (g = tid>>3 -> h index jbase+g, sk = tid&7 -> k-eighth).
// 4 gate rows x 32 k weights in registers; butterfly reduce over the 8
// k-slices; lane sk==0 does the activation with register-resident c.
__global__ void __cluster_dims__(8, 1, 1) __launch_bounds__(256, 1)
k2_lstm(const float* __restrict__ Wih) {
    __shared__ __align__(16) float h_buf[2][256];
    __shared__ unsigned long long mbar_s[2];

    int tid = threadIdx.x;
    int rank = blockIdx.x;
    int jbase = rank * 32;
    int sk = tid & 7;
    int g = tid >> 3;

    unsigned mb0 = smem_u32(&mbar_s[0]);
    unsigned mb1 = smem_u32(&mbar_s[1]);

    if (tid == 0) {
        mbar_init_(mb0, 1);
        mbar_init_(mb1, 1);
        mbar_arrive_expect(mb1, 1024);   // step 1 consume
        mbar_arrive_expect(mb0, 1024);   // step 2 consume
    }
    h_buf[0][tid] = g_feat[tid];

    float bi[4];
#pragma unroll
    for (int sec = 0; sec < 4; sec++) bi[sec] = g_bsum[sec * 256 + jbase + g];

    // weights into registers (rotated chunk order matching h access)
    ulonglong2 wr[4][8];
#pragma unroll
    for (int sec = 0; sec < 4; sec++) {
        const float* base = g_wsum + (sec * 256 + jbase + g) * 256 + sk * 32;
#pragma unroll
        for (int q = 0; q < 8; q++) {
            int qq = q ^ sk;
            wr[sec][q] = *(const ulonglong2*)(base + qq * 4);
        }
    }
    __syncthreads();
    cluster_sync_();   // remote mbarriers initialized

    float c = 0.f;
    int par0 = 0, par1 = 0;

    // ---- step 0: gates = W_ih @ feat ----
    {
        unsigned long long a[4][2];
#pragma unroll
        for (int sec = 0; sec < 4; sec++) { a[sec][0] = 0ull; a[sec][1] = 0ull; }
        const ulonglong2* hb = (const ulonglong2*)(&h_buf[0][sk * 32]);
#pragma unroll
        for (int q = 0; q < 8; q++) {
            int qq = q ^ sk;
            ulonglong2 hx = hb[qq];
#pragma unroll
            for (int sec = 0; sec < 4; sec++) {
                ulonglong2 wv = *(const ulonglong2*)
                    (Wih + (sec * 256 + jbase + g) * 256 + sk * 32 + qq * 4);
                FMA2(a[sec][0], wv.x, hx.x);
                FMA2(a[sec][1], wv.y, hx.y);
            }
        }
        float fs[4];
#pragma unroll
        for (int sec = 0; sec < 4; sec++) {
            float l0, h0, l1, h1;
            UNPACK64(l0, h0, a[sec][0]);
            UNPACK64(l1, h1, a[sec][1]);
            fs[sec] = (l0 + h0) + (l1 + h1);
        }
#pragma unroll
        for (int m = 1; m < 8; m <<= 1)
#pragma unroll
            for (int sec = 0; sec < 4; sec++)
                fs[sec] += __shfl_xor_sync(0xffffffffu, fs[sec], m);
        if (sk == 0) {
            float gi = sigmoidf_(fs[0] + bi[0]);
            float gf = sigmoidf_(fs[1] + bi[1]);
            float gg = tanhf(fs[2] + bi[2]);
            float go = sigmoidf_(fs[3] + bi[3]);
            c = gf * c + gi * gg;
            float h = go * tanhf(c);
            g_H[jbase + g] = h;
            unsigned da = smem_u32(&h_buf[1][jbase + g]);
#pragma unroll
            for (int rk = 0; rk < 8; rk++) st_async_remote(da, mb1, rk, h);
        }
    }

    // ---- steps 1..100 ----
    for (int s = 1; s <= 100; s++) {
        int b = s & 1;
        unsigned mb = b ? mb1 : mb0;
        mbar_wait_cluster(mb, b ? par1 : par0);
        if (b) par1 ^= 1; else par0 ^= 1;
        if (tid == 0 && s <= 98) mbar_arrive_expect(mb, 1024);

        unsigned long long a[4][2];
#pragma unroll
        for (int sec = 0; sec < 4; sec++) { a[sec][0] = 0ull; a[sec][1] = 0ull; }
        const ulonglong2* hb = (const ulonglong2*)(&h_buf[b][sk * 32]);
#pragma unroll
        for (int q = 0; q < 8; q++) {
            ulonglong2 hx = hb[q ^ sk];
#pragma unroll
            for (int sec = 0; sec < 4; sec++) {
                FMA2(a[sec][0], wr[sec][q].x, hx.x);
                FMA2(a[sec][1], wr[sec][q].y, hx.y);
            }
        }
        float fs[4];
#pragma unroll
        for (int sec = 0; sec < 4; sec++) {
            float l0, h0, l1, h1;
            UNPACK64(l0, h0, a[sec][0]);
            UNPACK64(l1, h1, a[sec][1]);
            fs[sec] = (l0 + h0) + (l1 + h1);
        }
#pragma unroll
        for (int m = 1; m < 8; m <<= 1)
#pragma unroll
            for (int sec = 0; sec < 4; sec++)
                fs[sec] += __shfl_xor_sync(0xffffffffu, fs[sec], m);

        if (sk == 0) {
            float gi = sigmoidf_(fs[0] + bi[0]);
            float gf = sigmoidf_(fs[1] + bi[1]);
            float gg = tanhf(fs[2] + bi[2]);
            float go = sigmoidf_(fs[3] + bi[3]);
            c = gf * c + gi * gg;
            float h = go * tanhf(c);
            g_H[s * 256 + jbase + g] = h;
            if (s < 100) {
                int nb = (s + 1) & 1;
                unsigned da = smem_u32(&h_buf[nb][jbase + g]);
                unsigned dm = nb ? mb1 : mb0;
#pragma unroll
                for (int rk = 0; rk < 8; rk++) st_async_remote(da, dm, rk, h);
            }
        }
    }
}

// ---------------- K3: OUT = relu(H @ W_dec^T + b) ----------------
// grid (391, 2): 128-vocab x 52/49-row tiles. Thread: 7 rows x 4 vocab.
// Double-buffered smem, register prefetch of next chunk, 1 sync/chunk.
// XOR-swizzled Ws staging (conflict-free STS + LDS.128 reads).
__global__ void __launch_bounds__(256, 2)
k3_decode(const float* __restrict__ W_dec,
          const float* __restrict__ b_dec,
          float* __restrict__ out) {
    extern __shared__ __align__(16) float sm[];
    float* Wb[2] = { sm, sm + 4096 };            // 32k x 128v each
    float* Hb[2] = { sm + 8192, sm + 8192 + 2048 }; // 32k x 64slots each

    int tid = threadIdx.x;
    int vbase = blockIdx.x * 128;
    int rbase = blockIdx.y * 52;
    int nrows = blockIdx.y == 0 ? 52 : (ROWS_OUT - 52);

    int vg = tid & 31;          // vocab quad
    int rg = tid >> 5;          // row group: rows rbase+rg*7 .. +6
    int v0 = vbase + vg * 4;

    // H staging identity for this thread
    int srow = tid & 63;
    int kqh = tid >> 6;         // 0..3 (and +4 for second float4)
    int hg = srow >> 3, hr = srow & 7;
    int lrow = hg * 7 + hr;
    bool hvalid = (hr < 7) && (lrow < nrows);
    int hrow = rbase + lrow;

    // W staging identity (4 float4s: F = tid + 256*q)
    // kq = F&7, vcol = F>>3
    unsigned long long acc0[4], acc1[4], acc2[4];
    float acc6[4];
#pragma unroll
    for (int c2 = 0; c2 < 4; c2++) {
        acc0[c2] = 0ull; acc1[c2] = 0ull; acc2[c2] = 0ull; acc6[c2] = 0.f;
    }

    const float4* Wd4 = (const float4*)W_dec;

    float4 w4[4];
    float4 h4[2];

    // prefetch chunk 0
#pragma unroll
    for (int q = 0; q < 4; q++) {
        int F = tid + 256 * q;
        int kq = F & 7, vcol = F >> 3;
        int v = vbase + vcol;
        w4[q] = (v < VOCAB) ? Wd4[v * 64 + 0 * 8 + kq]
                            : make_float4(0.f, 0.f, 0.f, 0.f);
    }
    if (hvalid) {
        const float4* hp4 = (const float4*)(g_H + hrow * 256);
        h4[0] = hp4[kqh];
        h4[1] = hp4[kqh + 4];
    } else {
        h4[0] = make_float4(0.f, 0.f, 0.f, 0.f);
        h4[1] = h4[0];
    }

    for (int kc = 0; kc < 8; kc++) {
        float* W = Wb[kc & 1];
        float* H = Hb[kc & 1];
        // store staged regs (swizzled)
#pragma unroll
        for (int q = 0; q < 4; q++) {
            int F = tid + 256 * q;
            int kq = F & 7, vcol = F >> 3;
            int colp = vcol ^ (kq << 2);
            W[(kq * 4 + 0) * 128 + colp] = w4[q].x;
            W[(kq * 4 + 1) * 128 + colp] = w4[q].y;
            W[(kq * 4 + 2) * 128 + colp] = w4[q].z;
            W[(kq * 4 + 3) * 128 + colp] = w4[q].w;
        }
        H[(kqh * 4 + 0) * 64 + srow] = h4[0].x;
        H[(kqh * 4 + 1) * 64 + srow] = h4[0].y;
        H[(kqh * 4 + 2) * 64 + srow] = h4[0].z;
        H[(kqh * 4 + 3) * 64 + srow] = h4[0].w;
        H[((kqh + 4) * 4 + 0) * 64 + srow] = h4[1].x;
        H[((kqh + 4) * 4 + 1) * 64 + srow] = h4[1].y;
        H[((kqh + 4) * 4 + 2) * 64 + srow] = h4[1].z;
        H[((kqh + 4) * 4 + 3) * 64 + srow] = h4[1].w;
        __syncthreads();

        // prefetch next chunk
        if (kc < 7) {
#pragma unroll
            for (int q = 0; q < 4; q++) {
                int F = tid + 256 * q;
                int kq = F & 7, vcol = F >> 3;
                int v = vbase + vcol;
                w4[q] = (v < VOCAB) ? Wd4[v * 64 + (kc + 1) * 8 + kq]
                                    : make_float4(0.f, 0.f, 0.f, 0.f);
            }
            if (hvalid) {
                const float4* hp4 = (const float4*)(g_H + hrow * 256 + (kc + 1) * 32);
                h4[0] = hp4[kqh];
                h4[1] = hp4[kqh + 4];
            }
        }

        // compute
#pragma unroll
        for (int kk = 0; kk < 32; kk++) {
            float4 wv = *(const float4*)(W + kk * 128 + ((vg ^ (kk >> 2)) << 2));
            unsigned long long wx, wy, wz, ww;
            DUP2(wx, wv.x); DUP2(wy, wv.y); DUP2(wz, wv.z); DUP2(ww, wv.w);
            const float* hp = H + kk * 64 + rg * 8;
            ulonglong2 hAB = *(const ulonglong2*)hp;       // rows 0-3
            unsigned long long hC = *(const unsigned long long*)(hp + 4); // rows 4-5
            float h6 = hp[6];
            FMA2(acc0[0], hAB.x, wx); FMA2(acc0[1], hAB.x, wy);
            FMA2(acc0[2], hAB.x, wz); FMA2(acc0[3], hAB.x, ww);
            FMA2(acc1[0], hAB.y, wx); FMA2(acc1[1], hAB.y, wy);
            FMA2(acc1[2], hAB.y, wz); FMA2(acc1[3], hAB.y, ww);
            FMA2(acc2[0], hC, wx);    FMA2(acc2[1], hC, wy);
            FMA2(acc2[2], hC, wz);    FMA2(acc2[3], hC, ww);
            acc6[0] = fmaf(h6, wv.x, acc6[0]);
            acc6[1] = fmaf(h6, wv.y, acc6[1]);
            acc6[2] = fmaf(h6, wv.z, acc6[2]);
            acc6[3] = fmaf(h6, wv.w, acc6[3]);
        }
    }

    bool vok = (v0 < VOCAB);
    float bb[4] = {0.f, 0.f, 0.f, 0.f};
    if (vok) {
        float4 bv = ((const float4*)b_dec)[v0 >> 2];
        bb[0] = bv.x; bb[1] = bv.y; bb[2] = bv.z; bb[3] = bv.w;
    }

    float rows[7][4];
#pragma unroll
    for (int c2 = 0; c2 < 4; c2++) {
        float lo, hi;
        UNPACK64(lo, hi, acc0[c2]); rows[0][c2] = lo; rows[1][c2] = hi;
        UNPACK64(lo, hi, acc1[c2]); rows[2][c2] = lo; rows[3][c2] = hi;
        UNPACK64(lo, hi, acc2[c2]); rows[4][c2] = lo; rows[5][c2] = hi;
        rows[6][c2] = acc6[c2];
    }
#pragma unroll
    for (int rr = 0; rr < 7; rr++) {
        int lr = rg * 7 + rr;
        if (vok && lr < nrows) {
            int row = rbase + lr;
            float4 o;
            o.x = fmaxf(rows[rr][0] + bb[0], 0.f);
            o.y = fmaxf(rows[rr][1] + bb[1], 0.f);
            o.z = fmaxf(rows[rr][2] + bb[2], 0.f);
            o.w = fmaxf(rows[rr][3] + bb[3], 0.f);
            *(float4*)(out + row * VOCAB + v0) = o;
        }
    }
}

// ---------------- launch ----------------
extern "C" void kernel_launch(void* const* d_in, const int* in_sizes, int n_in,
                              void* d_out, int out_size) {
    const float* board    = (const float*)d_in[0];
    const float* conv_w   = (const float*)d_in[1];
    const float* conv_b   = (const float*)d_in[2];
    const float* bn_gamma = (const float*)d_in[3];
    const float* bn_beta  = (const float*)d_in[4];
    const float* p        = (const float*)d_in[5];
    const float* W_lin    = (const float*)d_in[6];
    const float* b_lin    = (const float*)d_in[7];
    const float* W_ih     = (const float*)d_in[8];
    const float* b_ih     = (const float*)d_in[9];
    const float* W_hh     = (const float*)d_in[10];
    const float* b_hh     = (const float*)d_in[11];
    const float* W_dec    = (const float*)d_in[12];
    const float* b_dec    = (const float*)d_in[13];
    float* out = (float*)d_out;

    size_t sm3 = 12288 * sizeof(float);   // 48 KB dynamic
    cudaFuncSetAttribute(k3_decode, cudaFuncAttributeMaxDynamicSharedMemorySize, (int)sm3);

    k0_precompute<<<256, 256>>>(W_ih, W_hh, b_ih, b_hh, W_lin);
    k1_prep<<<1, 512>>>(board, conv_w, conv_b, bn_gamma, bn_beta, p, b_lin);
    k2_lstm<<<8, 256>>>(W_ih);
    dim3 g3((VOCAB + 127) / 128, 2);
    k3_decode<<<g3, 256, sm3>>>(W_dec, b_dec, out);
}

// round 4
// speedup vs baseline: 2.6875x; 1.0322x over previous
#include <cuda_runtime.h>
#include <math.h>

#define EMB 256
#define VOCAB 50000
#define ROWS_OUT 101
#define BN_EPS 1e-5f

// ---------------- packed f32x2 helpers ----------------
#define FMA2(acc, a, b) \
    asm("fma.rn.f32x2 %0, %1, %2, %0;" : "+l"(acc) : "l"(a), "l"(b))
#define UNPACK64(lo, hi, v) do { unsigned _ulo, _uhi; \
    asm("mov.b64 {%0, %1}, %2;" : "=r"(_ulo), "=r"(_uhi) : "l"(v)); \
    lo = __uint_as_float(_ulo); hi = __uint_as_float(_uhi); } while (0)
#define DUP2(d, f) do { unsigned _u = __float_as_uint(f); \
    asm("mov.b64 %0, {%1, %1};" : "=l"(d) : "r"(_u)); } while (0)

// ---------------- device scratch ----------------
__device__ float g_wsum[1024 * EMB];      // W_ih + W_hh
__device__ float g_bsum[1024];            // b_ih + b_hh
__device__ float g_WlinT[361 * EMB];      // W_lin transposed
__device__ float g_feat[EMB];
__device__ float g_H[ROWS_OUT * EMB];     // h vectors

// ---------------- K0 ----------------
__global__ void k0_precompute(const float* __restrict__ Wih,
                              const float* __restrict__ Whh,
                              const float* __restrict__ bih,
                              const float* __restrict__ bhh,
                              const float* __restrict__ Wlin) {
    int i = blockIdx.x * blockDim.x + threadIdx.x;
    int stride = gridDim.x * blockDim.x;
    for (int idx = i; idx < 1024 * EMB; idx += stride)
        g_wsum[idx] = Wih[idx] + Whh[idx];
    for (int idx = i; idx < 1024; idx += stride)
        g_bsum[idx] = bih[idx] + bhh[idx];
    for (int idx = i; idx < 361 * EMB; idx += stride) {
        int j = idx >> 8;
        int e = idx & 255;
        g_WlinT[idx] = Wlin[e * 361 + j];
    }
}

// ---------------- K1 ----------------
__device__ __forceinline__ float block_sum512(float v, float* red16) {
#pragma unroll
    for (int o = 16; o; o >>= 1) v += __shfl_xor_sync(0xffffffffu, v, o);
    __syncthreads();
    if ((threadIdx.x & 31) == 0) red16[threadIdx.x >> 5] = v;
    __syncthreads();
    float s = 0.f;
#pragma unroll
    for (int i = 0; i < 16; i++) s += red16[i];
    return s;
}

__global__ void k1_prep(const float* __restrict__ board,
                        const float* __restrict__ conv_w,
                        const float* __restrict__ conv_b,
                        const float* __restrict__ bn_gamma,
                        const float* __restrict__ bn_beta,
                        const float* __restrict__ p,
                        const float* __restrict__ b_lin) {
    __shared__ float A[441];
    __shared__ float B[441];
    __shared__ float d2s[361];
    __shared__ float red16[16];

    int tid = threadIdx.x;

    float w[9];
#pragma unroll
    for (int q = 0; q < 9; q++) w[q] = conv_w[q];
    float cbias = conv_b[0], gamma = bn_gamma[0], beta = bn_beta[0];

    if (tid < 441) { A[tid] = 0.f; B[tid] = 0.f; }
    __syncthreads();
    if (tid < 361) {
        int r = tid / 19, c = tid % 19;
        A[(r + 1) * 21 + (c + 1)] = board[tid];
    }
    __syncthreads();

    float* src = A;
    float* dst = B;

    const int types[8] = {0, 0, 1, 0, 1, 0, 1, 2};
    const int pidx[8]  = {0, 1, 2, 3, 4, 5, 6, 0};

    for (int st = 0; st < 8; st++) {
        float y = 0.f;
        int base = 0;
        if (tid < 361) {
            int r = tid / 19, c = tid % 19;
            base = (r + 1) * 21 + (c + 1);
#pragma unroll
            for (int ki = 0; ki < 3; ki++)
#pragma unroll
                for (int kj = 0; kj < 3; kj++)
                    y += w[ki * 3 + kj] * src[base + (ki - 1) * 21 + (kj - 1)];
            y += cbias;
        }
        float mu = block_sum512((tid < 361) ? y : 0.f, red16) * (1.f / 361.f);
        float d = (tid < 361) ? (y - mu) : 0.f;
        float var = block_sum512(d * d, red16) * (1.f / 361.f);
        float rstd = rsqrtf(var + BN_EPS);

        if (tid < 361) {
            float z = gamma * (y - mu) * rstd + beta;
            float v;
            int t = types[st];
            if (t == 0)      v = fmaxf(p[pidx[st]] * z, 0.f);
            else if (t == 1) v = fmaxf(p[pidx[st]] * z + d2s[tid], 0.f);
            else             v = fmaxf(z, 0.f);
            dst[base] = v;
            if (st == 0 || t == 1) d2s[tid] = v;
        }
        __syncthreads();
        float* tmp = src; src = dst; dst = tmp;
    }

    if (tid < 361) {
        int r = tid / 19, c = tid % 19;
        d2s[tid] = src[(r + 1) * 21 + (c + 1)];
    }
    __syncthreads();

    if (tid < 256) {
        float acc = b_lin[tid];
        for (int j = 0; j < 361; j++)
            acc += g_WlinT[j * 256 + tid] * d2s[j];
        g_feat[tid] = acc;
    }
}

// ---------------- K2: cluster-of-8 LSTM, mbarrier + st.async ----------------
__device__ __forceinline__ void cluster_sync_() {
    asm volatile("barrier.cluster.arrive.aligned;" ::: "memory");
    asm volatile("barrier.cluster.wait.aligned;" ::: "memory");
}
__device__ __forceinline__ unsigned smem_u32(const void* p) {
    unsigned a;
    asm("{ .reg .u64 t; cvta.to.shared.u64 t, %1; cvt.u32.u64 %0, t; }"
        : "=r"(a) : "l"(p));
    return a;
}
__device__ __forceinline__ void mbar_init_(unsigned addr, unsigned cnt) {
    asm volatile("mbarrier.init.shared.b64 [%0], %1;" :: "r"(addr), "r"(cnt) : "memory");
}
__device__ __forceinline__ void mbar_arrive_expect(unsigned addr, unsigned tx) {
    asm volatile("mbarrier.arrive.expect_tx.shared.b64 _, [%0], %1;"
                 :: "r"(addr), "r"(tx) : "memory");
}
__device__ __forceinline__ void mbar_wait_cluster(unsigned addr, unsigned parity) {
    unsigned done;
    asm volatile(
        "{\n\t.reg .pred p;\n\t"
        "mbarrier.try_wait.parity.acquire.cluster.shared::cta.b64 p, [%1], %2, 0x989680;\n\t"
        "selp.b32 %0, 1, 0, p;\n\t}"
        : "=r"(done) : "r"(addr), "r"(parity) : "memory");
    while (!done) {
        asm volatile(
            "{\n\t.reg .pred p;\n\t"
            "mbarrier.try_wait.parity.acquire.cluster.shared::cta.b64 p, [%1], %2, 0x989680;\n\t"
            "selp.b32 %0, 1, 0, p;\n\t}"
            : "=r"(done) : "r"(addr), "r"(parity) : "memory");
    }
}
__device__ __forceinline__ void st_async_remote(unsigned daddr, unsigned dmbar,
                                                int rk, float v) {
    unsigned ra, rm;
    asm volatile("mapa.shared::cluster.u32 %0, %1, %2;" : "=r"(ra) : "r"(daddr), "r"(rk));
    asm volatile("mapa.shared::cluster.u32 %0, %1, %2;" : "=r"(rm) : "r"(dmbar), "r"(rk));
    asm volatile("st.async.shared::cluster.mbarrier::complete_tx::bytes.f32 [%0], %1, [%2];"
                 :: "r"(ra), "f"(v), "r"(rm) : "memory");
}
__device__ __forceinline__ float sigmoidf_(float x) {
    return 1.f / (1.f + expf(-x));
}

// thread = (g = tid>>3 -> h index jbase+g, sk = tid&7 -> k-eighth).
// 4 gate rows x 32 k weights in registers; butterfly reduce over the 8
// k-slices; lane sk==0 does the activation with register-resident c.
__global__ void __cluster_dims__(8, 1, 1) __launch_bounds__(256, 1)
k2_lstm(const float* __restrict__ Wih) {
    __shared__ __align__(16) float h_buf[2][256];
    __shared__ unsigned long long mbar_s[2];

    int tid = threadIdx.x;
    int rank = blockIdx.x;
    int jbase = rank * 32;
    int sk = tid & 7;
    int g = tid >> 3;

    unsigned mb0 = smem_u32(&mbar_s[0]);
    unsigned mb1 = smem_u32(&mbar_s[1]);

    if (tid == 0) {
        mbar_init_(mb0, 1);
        mbar_init_(mb1, 1);
        mbar_arrive_expect(mb1, 1024);   // step 1 consume
        mbar_arrive_expect(mb0, 1024);   // step 2 consume
    }
    h_buf[0][tid] = g_feat[tid];

    float bi[4];
#pragma unroll
    for (int sec = 0; sec < 4; sec++) bi[sec] = g_bsum[sec * 256 + jbase + g];

    // weights into registers (rotated chunk order matching h access)
    ulonglong2 wr[4][8];
#pragma unroll
    for (int sec = 0; sec < 4; sec++) {
        const float* base = g_wsum + (sec * 256 + jbase + g) * 256 + sk * 32;
#pragma unroll
        for (int q = 0; q < 8; q++) {
            int qq = q ^ sk;
            wr[sec][q] = *(const ulonglong2*)(base + qq * 4);
        }
    }
    __syncthreads();
    cluster_sync_();   // remote mbarriers initialized

    float c = 0.f;
    int par0 = 0, par1 = 0;

    // ---- step 0: gates = W_ih @ feat ----
    {
        unsigned long long a[4][2];
#pragma unroll
        for (int sec = 0; sec < 4; sec++) { a[sec][0] = 0ull; a[sec][1] = 0ull; }
        const ulonglong2* hb = (const ulonglong2*)(&h_buf[0][sk * 32]);
#pragma unroll
        for (int q = 0; q < 8; q++) {
            int qq = q ^ sk;
            ulonglong2 hx = hb[qq];
#pragma unroll
            for (int sec = 0; sec < 4; sec++) {
                ulonglong2 wv = *(const ulonglong2*)
                    (Wih + (sec * 256 + jbase + g) * 256 + sk * 32 + qq * 4);
                FMA2(a[sec][0], wv.x, hx.x);
                FMA2(a[sec][1], wv.y, hx.y);
            }
        }
        float fs[4];
#pragma unroll
        for (int sec = 0; sec < 4; sec++) {
            float l0, h0, l1, h1;
            UNPACK64(l0, h0, a[sec][0]);
            UNPACK64(l1, h1, a[sec][1]);
            fs[sec] = (l0 + h0) + (l1 + h1);
        }
#pragma unroll
        for (int m = 1; m < 8; m <<= 1)
#pragma unroll
            for (int sec = 0; sec < 4; sec++)
                fs[sec] += __shfl_xor_sync(0xffffffffu, fs[sec], m);
        if (sk == 0) {
            float gi = sigmoidf_(fs[0] + bi[0]);
            float gf = sigmoidf_(fs[1] + bi[1]);
            float gg = tanhf(fs[2] + bi[2]);
            float go = sigmoidf_(fs[3] + bi[3]);
            c = gf * c + gi * gg;
            float h = go * tanhf(c);
            g_H[jbase + g] = h;
            unsigned da = smem_u32(&h_buf[1][jbase + g]);
#pragma unroll
            for (int rk = 0; rk < 8; rk++) st_async_remote(da, mb1, rk, h);
        }
    }

    // ---- steps 1..100 ----
    for (int s = 1; s <= 100; s++) {
        int b = s & 1;
        unsigned mb = b ? mb1 : mb0;
        mbar_wait_cluster(mb, b ? par1 : par0);
        if (b) par1 ^= 1; else par0 ^= 1;
        if (tid == 0 && s <= 98) mbar_arrive_expect(mb, 1024);

        unsigned long long a[4][2];
#pragma unroll
        for (int sec = 0; sec < 4; sec++) { a[sec][0] = 0ull; a[sec][1] = 0ull; }
        const ulonglong2* hb = (const ulonglong2*)(&h_buf[b][sk * 32]);
#pragma unroll
        for (int q = 0; q < 8; q++) {
            ulonglong2 hx = hb[q ^ sk];
#pragma unroll
            for (int sec = 0; sec < 4; sec++) {
                FMA2(a[sec][0], wr[sec][q].x, hx.x);
                FMA2(a[sec][1], wr[sec][q].y, hx.y);
            }
        }
        float fs[4];
#pragma unroll
        for (int sec = 0; sec < 4; sec++) {
            float l0, h0, l1, h1;
            UNPACK64(l0, h0, a[sec][0]);
            UNPACK64(l1, h1, a[sec][1]);
            fs[sec] = (l0 + h0) + (l1 + h1);
        }
#pragma unroll
        for (int m = 1; m < 8; m <<= 1)
#pragma unroll
            for (int sec = 0; sec < 4; sec++)
                fs[sec] += __shfl_xor_sync(0xffffffffu, fs[sec], m);

        if (sk == 0) {
            float gi = sigmoidf_(fs[0] + bi[0]);
            float gf = sigmoidf_(fs[1] + bi[1]);
            float gg = tanhf(fs[2] + bi[2]);
            float go = sigmoidf_(fs[3] + bi[3]);
            c = gf * c + gi * gg;
            float h = go * tanhf(c);
            g_H[s * 256 + jbase + g] = h;
            if (s < 100) {
                int nb = (s + 1) & 1;
                unsigned da = smem_u32(&h_buf[nb][jbase + g]);
                unsigned dm = nb ? mb1 : mb0;
#pragma unroll
                for (int rk = 0; rk < 8; rk++) st_async_remote(da, dm, rk, h);
            }
        }
    }
}

// ---------------- K3: OUT = relu(H @ W_dec^T + b) ----------------
// grid (391, 2): 128-vocab x 52/49-row tiles. Thread: 7 rows x 4 vocab.
// Double-buffered smem, register prefetch of next chunk, 1 sync/chunk.
// XOR-swizzled Ws staging (conflict-free STS + LDS.128 reads).
__global__ void __launch_bounds__(256, 2)
k3_decode(const float* __restrict__ W_dec,
          const float* __restrict__ b_dec,
          float* __restrict__ out) {
    extern __shared__ __align__(16) float sm[];
    float* Wb[2] = { sm, sm + 4096 };            // 32k x 128v each
    float* Hb[2] = { sm + 8192, sm + 8192 + 2048 }; // 32k x 64slots each

    int tid = threadIdx.x;
    int vbase = blockIdx.x * 128;
    int rbase = blockIdx.y * 52;
    int nrows = blockIdx.y == 0 ? 52 : (ROWS_OUT - 52);

    int vg = tid & 31;          // vocab quad
    int rg = tid >> 5;          // row group: rows rbase+rg*7 .. +6
    int v0 = vbase + vg * 4;

    // H staging identity for this thread
    int srow = tid & 63;
    int kqh = tid >> 6;         // 0..3 (and +4 for second float4)
    int hg = srow >> 3, hr = srow & 7;
    int lrow = hg * 7 + hr;
    bool hvalid = (hr < 7) && (lrow < nrows);
    int hrow = rbase + lrow;

    // W staging identity (4 float4s: F = tid + 256*q)
    // kq = F&7, vcol = F>>3
    unsigned long long acc0[4], acc1[4], acc2[4];
    float acc6[4];
#pragma unroll
    for (int c2 = 0; c2 < 4; c2++) {
        acc0[c2] = 0ull; acc1[c2] = 0ull; acc2[c2] = 0ull; acc6[c2] = 0.f;
    }

    const float4* Wd4 = (const float4*)W_dec;

    float4 w4[4];
    float4 h4[2];

    // prefetch chunk 0
#pragma unroll
    for (int q = 0; q < 4; q++) {
        int F = tid + 256 * q;
        int kq = F & 7, vcol = F >> 3;
        int v = vbase + vcol;
        w4[q] = (v < VOCAB) ? Wd4[v * 64 + 0 * 8 + kq]
                            : make_float4(0.f, 0.f, 0.f, 0.f);
    }
    if (hvalid) {
        const float4* hp4 = (const float4*)(g_H + hrow * 256);
        h4[0] = hp4[kqh];
        h4[1] = hp4[kqh + 4];
    } else {
        h4[0] = make_float4(0.f, 0.f, 0.f, 0.f);
        h4[1] = h4[0];
    }

    for (int kc = 0; kc < 8; kc++) {
        float* W = Wb[kc & 1];
        float* H = Hb[kc & 1];
        // store staged regs (swizzled)
#pragma unroll
        for (int q = 0; q < 4; q++) {
            int F = tid + 256 * q;
            int kq = F & 7, vcol = F >> 3;
            int colp = vcol ^ (kq << 2);
            W[(kq * 4 + 0) * 128 + colp] = w4[q].x;
            W[(kq * 4 + 1) * 128 + colp] = w4[q].y;
            W[(kq * 4 + 2) * 128 + colp] = w4[q].z;
            W[(kq * 4 + 3) * 128 + colp] = w4[q].w;
        }
        H[(kqh * 4 + 0) * 64 + srow] = h4[0].x;
        H[(kqh * 4 + 1) * 64 + srow] = h4[0].y;
        H[(kqh * 4 + 2) * 64 + srow] = h4[0].z;
        H[(kqh * 4 + 3) * 64 + srow] = h4[0].w;
        H[((kqh + 4) * 4 + 0) * 64 + srow] = h4[1].x;
        H[((kqh + 4) * 4 + 1) * 64 + srow] = h4[1].y;
        H[((kqh + 4) * 4 + 2) * 64 + srow] = h4[1].z;
        H[((kqh + 4) * 4 + 3) * 64 + srow] = h4[1].w;
        __syncthreads();

        // prefetch next chunk
        if (kc < 7) {
#pragma unroll
            for (int q = 0; q < 4; q++) {
                int F = tid + 256 * q;
                int kq = F & 7, vcol = F >> 3;
                int v = vbase + vcol;
                w4[q] = (v < VOCAB) ? Wd4[v * 64 + (kc + 1) * 8 + kq]
                                    : make_float4(0.f, 0.f, 0.f, 0.f);
            }
            if (hvalid) {
                const float4* hp4 = (const float4*)(g_H + hrow * 256 + (kc + 1) * 32);
                h4[0] = hp4[kqh];
                h4[1] = hp4[kqh + 4];
            }
        }

        // compute
#pragma unroll
        for (int kk = 0; kk < 32; kk++) {
            float4 wv = *(const float4*)(W + kk * 128 + ((vg ^ (kk >> 2)) << 2));
            unsigned long long wx, wy, wz, ww;
            DUP2(wx, wv.x); DUP2(wy, wv.y); DUP2(wz, wv.z); DUP2(ww, wv.w);
            const float* hp = H + kk * 64 + rg * 8;
            ulonglong2 hAB = *(const ulonglong2*)hp;       // rows 0-3
            unsigned long long hC = *(const unsigned long long*)(hp + 4); // rows 4-5
            float h6 = hp[6];
            FMA2(acc0[0], hAB.x, wx); FMA2(acc0[1], hAB.x, wy);
            FMA2(acc0[2], hAB.x, wz); FMA2(acc0[3], hAB.x, ww);
            FMA2(acc1[0], hAB.y, wx); FMA2(acc1[1], hAB.y, wy);
            FMA2(acc1[2], hAB.y, wz); FMA2(acc1[3], hAB.y, ww);
            FMA2(acc2[0], hC, wx);    FMA2(acc2[1], hC, wy);
            FMA2(acc2[2], hC, wz);    FMA2(acc2[3], hC, ww);
            acc6[0] = fmaf(h6, wv.x, acc6[0]);
            acc6[1] = fmaf(h6, wv.y, acc6[1]);
            acc6[2] = fmaf(h6, wv.z, acc6[2]);
            acc6[3] = fmaf(h6, wv.w, acc6[3]);
        }
    }

    bool vok = (v0 < VOCAB);
    float bb[4] = {0.f, 0.f, 0.f, 0.f};
    if (vok) {
        float4 bv = ((const float4*)b_dec)[v0 >> 2];
        bb[0] = bv.x; bb[1] = bv.y; bb[2] = bv.z; bb[3] = bv.w;
    }

    float rows[7][4];
#pragma unroll
    for (int c2 = 0; c2 < 4; c2++) {
        float lo, hi;
        UNPACK64(lo, hi, acc0[c2]); rows[0][c2] = lo; rows[1][c2] = hi;
        UNPACK64(lo, hi, acc1[c2]); rows[2][c2] = lo; rows[3][c2] = hi;
        UNPACK64(lo, hi, acc2[c2]); rows[4][c2] = lo; rows[5][c2] = hi;
        rows[6][c2] = acc6[c2];
    }
#pragma unroll
    for (int rr = 0; rr < 7; rr++) {
        int lr = rg * 7 + rr;
        if (vok && lr < nrows) {
            int row = rbase + lr;
            float4 o;
            o.x = fmaxf(rows[rr][0] + bb[0], 0.f);
            o.y = fmaxf(rows[rr][1] + bb[1], 0.f);
            o.z = fmaxf(rows[rr][2] + bb[2], 0.f);
            o.w = fmaxf(rows[rr][3] + bb[3], 0.f);
            *(float4*)(out + row * VOCAB + v0) = o;
        }
    }
}

// ---------------- launch ----------------
extern "C" void kernel_launch(void* const* d_in, const int* in_sizes, int n_in,
                              void* d_out, int out_size) {
    const float* board    = (const float*)d_in[0];
    const float* conv_w   = (const float*)d_in[1];
    const float* conv_b   = (const float*)d_in[2];
    const float* bn_gamma = (const float*)d_in[3];
    const float* bn_beta  = (const float*)d_in[4];
    const float* p        = (const float*)d_in[5];
    const float* W_lin    = (const float*)d_in[6];
    const float* b_lin    = (const float*)d_in[7];
    const float* W_ih     = (const float*)d_in[8];
    const float* b_ih     = (const float*)d_in[9];
    const float* W_hh     = (const float*)d_in[10];
    const float* b_hh     = (const float*)d_in[11];
    const float* W_dec    = (const float*)d_in[12];
    const float* b_dec    = (const float*)d_in[13];
    float* out = (float*)d_out;

    size_t sm3 = 12288 * sizeof(float);   // 48 KB dynamic
    cudaFuncSetAttribute(k3_decode, cudaFuncAttributeMaxDynamicSharedMemorySize, (int)sm3);

    k0_precompute<<<256, 256>>>(W_ih, W_hh, b_ih, b_hh, W_lin);
    k1_prep<<<1, 512>>>(board, conv_w, conv_b, bn_gamma, bn_beta, p, b_lin);
    k2_lstm<<<8, 256>>>(W_ih);
    dim3 g3((VOCAB + 127) / 128, 2);
    k3_decode<<<g3, 256, sm3>>>(W_dec, b_dec, out);
}